// round 1
// baseline (speedup 1.0000x reference)
#include <cuda_runtime.h>
#include <math.h>

// Problem constants
#define BB   8
#define TT   2048
#define DD   512
#define BT   (BB*TT)          // 16384
#define DMID (3*DD)           // 1536

// ---------------- scratch (device globals; no allocation allowed) -------------
__device__ float g_lo [BT*DD];           // left_out
__device__ float g_ro [BT*DD];           // right_out
__device__ float g_body[BT*DD];          // body_out
__device__ float g_S  [(long long)BB*TT*TT]; // attention scores (134MB)
__device__ float g_t1 [BT*DD];
__device__ float g_t2 [BT*DD];
__device__ float g_mid[BT*DMID];

// ---------------- helpers ------------------------------------------------------
__device__ __forceinline__ float gelu_f(float x) {
    return 0.5f * x * (1.0f + erff(x * 0.7071067811865476f));
}

// ---------------- GEMM: C[M,N] = A[M,K] @ B  (B is [K,N] or, TRANSB, [N,K]) ----
// 128x128 block tile, 8x8 per-thread microtile, BK=8, 256 threads.
// EPI: 0=none, 1=+bias, 2=gelu(+bias), 3=gelu(+bias)+res
template<int EPI, bool TRANSB>
__global__ void __launch_bounds__(256)
gemm128(const float* __restrict__ A, const float* __restrict__ Bm,
        const float* __restrict__ bias, const float* __restrict__ res,
        float* __restrict__ C, int M, int N, int K,
        long long sA, long long sB, long long sC)
{
    __shared__ float As[8][128];
    __shared__ float Bs[8][128];

    const int tid = threadIdx.x;
    const int tx  = tid & 15;
    const int ty  = tid >> 4;
    const long long m0 = (long long)blockIdx.y * 128;
    const long long n0 = (long long)blockIdx.x * 128;

    const float* Ab = A  + (long long)blockIdx.z * sA;
    const float* Bb = Bm + (long long)blockIdx.z * sB;
    float*       Cb = C  + (long long)blockIdx.z * sC;
    const float* Rb = (EPI == 3) ? (res + (long long)blockIdx.z * sC) : nullptr;

    // A load pattern: each thread loads one float4 (row = tid>>1, kquad = tid&1)
    const int la_m = tid >> 1;             // 0..127
    const int la_k = (tid & 1) << 2;       // 0 or 4
    const float* aptr = Ab + (m0 + la_m) * (long long)K + la_k;

    // B load pattern
    const int lb_k = tid >> 5;             // 0..7   (NN)
    const int lb_n = (tid & 31) << 2;      // 0..124 (NN)
    const float* bptr;
    if (TRANSB) bptr = Bb + (n0 + la_m) * (long long)K + la_k;     // row-of-B^T
    else        bptr = Bb + (long long)lb_k * N + n0 + lb_n;

    float acc[8][8];
    #pragma unroll
    for (int i = 0; i < 8; i++)
        #pragma unroll
        for (int j = 0; j < 8; j++) acc[i][j] = 0.0f;

    for (int k0 = 0; k0 < K; k0 += 8) {
        float4 av = *(const float4*)aptr;  aptr += 8;
        As[la_k+0][la_m] = av.x;
        As[la_k+1][la_m] = av.y;
        As[la_k+2][la_m] = av.z;
        As[la_k+3][la_m] = av.w;

        if (TRANSB) {
            float4 bv = *(const float4*)bptr;  bptr += 8;
            Bs[la_k+0][la_m] = bv.x;
            Bs[la_k+1][la_m] = bv.y;
            Bs[la_k+2][la_m] = bv.z;
            Bs[la_k+3][la_m] = bv.w;
        } else {
            float4 bv = *(const float4*)bptr;  bptr += (long long)8 * N;
            *(float4*)&Bs[lb_k][lb_n] = bv;
        }
        __syncthreads();

        #pragma unroll
        for (int kk = 0; kk < 8; kk++) {
            float4 a0 = *(const float4*)&As[kk][ty << 3];
            float4 a1 = *(const float4*)&As[kk][(ty << 3) + 4];
            float4 b0 = *(const float4*)&Bs[kk][tx << 3];
            float4 b1 = *(const float4*)&Bs[kk][(tx << 3) + 4];
            float a[8] = {a0.x,a0.y,a0.z,a0.w,a1.x,a1.y,a1.z,a1.w};
            float b[8] = {b0.x,b0.y,b0.z,b0.w,b1.x,b1.y,b1.z,b1.w};
            #pragma unroll
            for (int i = 0; i < 8; i++)
                #pragma unroll
                for (int j = 0; j < 8; j++)
                    acc[i][j] = fmaf(a[i], b[j], acc[i][j]);
        }
        __syncthreads();
    }

    // epilogue
    float bv[8];
    if (EPI >= 1) {
        #pragma unroll
        for (int j = 0; j < 8; j++) bv[j] = bias[n0 + (tx << 3) + j];
    }
    #pragma unroll
    for (int i = 0; i < 8; i++) {
        long long row = m0 + (ty << 3) + i;
        long long off = row * (long long)N + n0 + (tx << 3);
        float v[8];
        #pragma unroll
        for (int j = 0; j < 8; j++) {
            float x = acc[i][j];
            if (EPI >= 1) x += bv[j];
            if (EPI >= 2) x = gelu_f(x);
            if (EPI == 3) x += Rb[off + j];
            v[j] = x;
        }
        *(float4*)&Cb[off]     = make_float4(v[0], v[1], v[2], v[3]);
        *(float4*)&Cb[off + 4] = make_float4(v[4], v[5], v[6], v[7]);
    }
}

// ---------------- softmax over rows of length 2048 (256 threads/row) ----------
__global__ void __launch_bounds__(256)
softmax2048(float* __restrict__ S)
{
    __shared__ float sh[8];
    const long long row = blockIdx.x;
    float* p = S + row * (long long)TT;
    const int tid = threadIdx.x;
    const int lane = tid & 31, warp = tid >> 5;

    float4 x0 = *(const float4*)(p + tid * 8);
    float4 x1 = *(const float4*)(p + tid * 8 + 4);
    float x[8] = {x0.x,x0.y,x0.z,x0.w,x1.x,x1.y,x1.z,x1.w};

    float m = x[0];
    #pragma unroll
    for (int i = 1; i < 8; i++) m = fmaxf(m, x[i]);
    #pragma unroll
    for (int o = 16; o > 0; o >>= 1) m = fmaxf(m, __shfl_xor_sync(0xffffffffu, m, o));
    if (lane == 0) sh[warp] = m;
    __syncthreads();
    if (tid == 0) {
        float mm = sh[0];
        #pragma unroll
        for (int w = 1; w < 8; w++) mm = fmaxf(mm, sh[w]);
        sh[0] = mm;
    }
    __syncthreads();
    const float rmax = sh[0];
    __syncthreads();

    float e[8], s = 0.0f;
    #pragma unroll
    for (int i = 0; i < 8; i++) { e[i] = __expf(x[i] - rmax); s += e[i]; }
    #pragma unroll
    for (int o = 16; o > 0; o >>= 1) s += __shfl_xor_sync(0xffffffffu, s, o);
    if (lane == 0) sh[warp] = s;
    __syncthreads();
    if (tid == 0) {
        float ss = 0.0f;
        #pragma unroll
        for (int w = 0; w < 8; w++) ss += sh[w];
        sh[0] = ss;
    }
    __syncthreads();
    const float inv = 1.0f / sh[0];

    #pragma unroll
    for (int i = 0; i < 8; i++) e[i] *= inv;
    *(float4*)(p + tid * 8)     = make_float4(e[0], e[1], e[2], e[3]);
    *(float4*)(p + tid * 8 + 4) = make_float4(e[4], e[5], e[6], e[7]);
}

// ---------------- layernorm over rows of length 512 (128 threads/row) ---------
__global__ void __launch_bounds__(128)
layernorm512(const float* __restrict__ X, float* __restrict__ Y,
             const float* __restrict__ g, const float* __restrict__ b)
{
    __shared__ float shs[4], shq[4];
    const long long row = blockIdx.x;
    const float* x = X + row * (long long)DD;
    const int tid = threadIdx.x;
    const int lane = tid & 31, warp = tid >> 5;

    float4 v = *(const float4*)(x + tid * 4);
    float s = v.x + v.y + v.z + v.w;
    float q = v.x*v.x + v.y*v.y + v.z*v.z + v.w*v.w;
    #pragma unroll
    for (int o = 16; o > 0; o >>= 1) {
        s += __shfl_xor_sync(0xffffffffu, s, o);
        q += __shfl_xor_sync(0xffffffffu, q, o);
    }
    if (lane == 0) { shs[warp] = s; shq[warp] = q; }
    __syncthreads();
    if (tid == 0) {
        float ts = shs[0]+shs[1]+shs[2]+shs[3];
        float tq = shq[0]+shq[1]+shq[2]+shq[3];
        shs[0] = ts; shq[0] = tq;
    }
    __syncthreads();
    const float mu  = shs[0] * (1.0f / DD);
    const float var = shq[0] * (1.0f / DD) - mu * mu;
    const float r = rsqrtf(var + 1e-5f);

    float4 gg = *(const float4*)(g + tid * 4);
    float4 bb = *(const float4*)(b + tid * 4);
    float4 o;
    o.x = (v.x - mu) * r * gg.x + bb.x;
    o.y = (v.y - mu) * r * gg.y + bb.y;
    o.z = (v.z - mu) * r * gg.z + bb.z;
    o.w = (v.w - mu) * r * gg.w + bb.w;
    *(float4*)(Y + row * (long long)DD + tid * 4) = o;
}

// ---------------- launch -------------------------------------------------------
extern "C" void kernel_launch(void* const* d_in, const int* in_sizes, int n_in,
                              void* d_out, int out_size)
{
    const float* left  = (const float*)d_in[0];
    const float* right = (const float*)d_in[1];
    const float* body  = (const float*)d_in[2];
    const float* Wl = (const float*)d_in[3];  const float* bl = (const float*)d_in[4];
    const float* Wr = (const float*)d_in[5];  const float* br = (const float*)d_in[6];
    const float* Wb = (const float*)d_in[7];  const float* bbias = (const float*)d_in[8];
    const float* Wo = (const float*)d_in[9];  const float* bo = (const float*)d_in[10];
    const float* ln_g = (const float*)d_in[11]; const float* ln_b = (const float*)d_in[12];
    const float* W1 = (const float*)d_in[13]; const float* b1 = (const float*)d_in[14];
    const float* lg2 = (const float*)d_in[15]; const float* lb2 = (const float*)d_in[16];
    const float* W2 = (const float*)d_in[17]; const float* b2 = (const float*)d_in[18];
    const float* W3 = (const float*)d_in[19]; const float* b3 = (const float*)d_in[20];
    float* out = (float*)d_out;

    float *lo, *ro, *bod, *S, *t1, *t2, *mid;
    cudaGetSymbolAddress((void**)&lo,  g_lo);
    cudaGetSymbolAddress((void**)&ro,  g_ro);
    cudaGetSymbolAddress((void**)&bod, g_body);
    cudaGetSymbolAddress((void**)&S,   g_S);
    cudaGetSymbolAddress((void**)&t1,  g_t1);
    cudaGetSymbolAddress((void**)&t2,  g_t2);
    cudaGetSymbolAddress((void**)&mid, g_mid);

    const long long sTD = (long long)TT * DD;      // per-batch token-feature stride
    const long long sTT = (long long)TT * TT;      // per-batch score stride

    // 1-3) input projections + GELU  [16384,512] = [16384,512]@[512,512]
    gemm128<2,false><<<dim3(DD/128, BT/128, 1), 256>>>(left,  Wl, bl,    nullptr, lo,  BT, DD, DD, 0, 0, 0);
    gemm128<2,false><<<dim3(DD/128, BT/128, 1), 256>>>(right, Wr, br,    nullptr, ro,  BT, DD, DD, 0, 0, 0);
    gemm128<2,false><<<dim3(DD/128, BT/128, 1), 256>>>(body,  Wb, bbias, nullptr, bod, BT, DD, DD, 0, 0, 0);

    // 4) S = right_out @ left_out^T  (batched, NT)
    gemm128<0,true><<<dim3(TT/128, TT/128, BB), 256>>>(ro, lo, nullptr, nullptr, S,
                                                       TT, TT, DD, sTD, sTD, sTT);
    // 5) row softmax
    softmax2048<<<BB * TT, 256>>>(S);

    // 6) fuse_pre = S @ body_out  (batched, NN, K=2048)
    gemm128<0,false><<<dim3(DD/128, TT/128, BB), 256>>>(S, bod, nullptr, nullptr, t1,
                                                        TT, DD, TT, sTT, sTD, sTD);
    // 7) fuse = LN(fuse_pre @ Wo + bo)
    gemm128<1,false><<<dim3(DD/128, BT/128, 1), 256>>>(t1, Wo, bo, nullptr, t2, BT, DD, DD, 0, 0, 0);
    layernorm512<<<BT, 128>>>(t2, t1, ln_g, ln_b);

    // 8) h = gelu(fuse @ W1 + b1) + fuse ; LN
    gemm128<3,false><<<dim3(DD/128, BT/128, 1), 256>>>(t1, W1, b1, t1, t2, BT, DD, DD, 0, 0, 0);
    layernorm512<<<BT, 128>>>(t2, t1, lg2, lb2);

    // 9) mid = gelu(h @ W2 + b2)  [16384,1536]
    gemm128<2,false><<<dim3(DMID/128, BT/128, 1), 256>>>(t1, W2, b2, nullptr, mid, BT, DMID, DD, 0, 0, 0);

    // 10) out = mid @ W3 + b3  [16384,512], K=1536
    gemm128<1,false><<<dim3(DD/128, BT/128, 1), 256>>>(mid, W3, b3, nullptr, out, BT, DD, DMID, 0, 0, 0);
}

// round 3
// speedup vs baseline: 2.0291x; 2.0291x over previous
#include <cuda_runtime.h>
#include <cuda_bf16.h>
#include <cstdint>
#include <math.h>

#define BB   8
#define TT   2048
#define DD   512
#define BT   (BB*TT)
#define DMID (3*DD)

// ---------------- scratch -------------------------------------------------------
__device__ __align__(16) float g_S[(long long)BB*TT*TT];          // 134MB
__device__ __align__(16) __nv_bfloat16 g_Sh[(long long)BB*TT*TT];
__device__ __align__(16) __nv_bfloat16 g_Sl[(long long)BB*TT*TT];
__device__ __align__(16) __nv_bfloat16 g_eh[BT*DD],  g_el[BT*DD];
__device__ __align__(16) __nv_bfloat16 g_loh[BT*DD], g_lol[BT*DD];
__device__ __align__(16) __nv_bfloat16 g_roh[BT*DD], g_rol[BT*DD];
__device__ __align__(16) __nv_bfloat16 g_bth[BT*DD], g_btl[BT*DD];
__device__ __align__(16) __nv_bfloat16 g_t1h[BT*DD], g_t1l[BT*DD];
__device__ __align__(16) float g_t2 [BT*DD];
__device__ __align__(16) float g_ln1[BT*DD];
__device__ __align__(16) __nv_bfloat16 g_l1h[BT*DD], g_l1l[BT*DD];
__device__ __align__(16) __nv_bfloat16 g_l2h[BT*DD], g_l2l[BT*DD];
__device__ __align__(16) __nv_bfloat16 g_mh[BT*DMID], g_ml[BT*DMID];
__device__ __align__(16) __nv_bfloat16 g_WlTh[DD*DD],  g_WlTl[DD*DD];
__device__ __align__(16) __nv_bfloat16 g_WrTh[DD*DD],  g_WrTl[DD*DD];
__device__ __align__(16) __nv_bfloat16 g_WbTh[DD*DD],  g_WbTl[DD*DD];
__device__ __align__(16) __nv_bfloat16 g_WoTh[DD*DD],  g_WoTl[DD*DD];
__device__ __align__(16) __nv_bfloat16 g_W1Th[DD*DD],  g_W1Tl[DD*DD];
__device__ __align__(16) __nv_bfloat16 g_W2Th[DMID*DD],g_W2Tl[DMID*DD];
__device__ __align__(16) __nv_bfloat16 g_W3Th[DD*DMID],g_W3Tl[DD*DMID];

// ---------------- helpers -------------------------------------------------------
__device__ __forceinline__ float gelu_f(float x) {
    return 0.5f * x * (1.0f + erff(x * 0.7071067811865476f));
}
__device__ __forceinline__ uint32_t smem_u32(const void* p) {
    uint32_t a;
    asm("{ .reg .u64 t; cvta.to.shared.u64 t, %1; cvt.u32.u64 %0, t; }" : "=r"(a) : "l"(p));
    return a;
}
__device__ __forceinline__ void cpa16(uint32_t dst, const void* src) {
    asm volatile("cp.async.cg.shared.global [%0], [%1], 16;" :: "r"(dst), "l"(src));
}
__device__ __forceinline__ void ldsm4(uint32_t* r, uint32_t a) {
    asm volatile("ldmatrix.sync.aligned.m8n8.x4.shared.b16 {%0,%1,%2,%3}, [%4];"
                 : "=r"(r[0]), "=r"(r[1]), "=r"(r[2]), "=r"(r[3]) : "r"(a));
}
__device__ __forceinline__ void mma16816(float* d, const uint32_t* a, const uint32_t* b) {
    asm volatile("mma.sync.aligned.m16n8k16.row.col.f32.bf16.bf16.f32 "
                 "{%0,%1,%2,%3}, {%4,%5,%6,%7}, {%8,%9}, {%0,%1,%2,%3};"
                 : "+f"(d[0]), "+f"(d[1]), "+f"(d[2]), "+f"(d[3])
                 : "r"(a[0]), "r"(a[1]), "r"(a[2]), "r"(a[3]), "r"(b[0]), "r"(b[1]));
}
__device__ __forceinline__ void split2(float v0, float v1, __nv_bfloat162& h, __nv_bfloat162& l) {
    h = __floats2bfloat162_rn(v0, v1);
    float2 f = __bfloat1622float2(h);
    l = __floats2bfloat162_rn(v0 - f.x, v1 - f.y);
}

#define STG 40960u            // stage bytes: Ah 10240 | Al 10240 | Bh 10240 | Bl 10240
#define SMEM_BYTES (3*40960)  // 3-stage pipeline

// fill one 128x32(k) chunk of A and B (all 4 split arrays) via cp.async
__device__ __forceinline__ void fill_stage(uint32_t sb,
    const __nv_bfloat16* Abh, const __nv_bfloat16* Abl,
    const __nv_bfloat16* Bbh, const __nv_bfloat16* Bbl,
    long long m0, long long n0, int k0, int K, int tid)
{
    #pragma unroll
    for (int j = 0; j < 2; j++) {
        const int id  = tid * 2 + j;          // 0..511
        const int row = id >> 2, ch = id & 3;
        const uint32_t so = (uint32_t)(row * 80 + ch * 16);
        const long long ao = (m0 + row) * (long long)K + k0 + ch * 8;
        const long long bo = (n0 + row) * (long long)K + k0 + ch * 8;
        cpa16(sb +          so, Abh + ao);
        cpa16(sb + 10240u + so, Abl + ao);
        cpa16(sb + 20480u + so, Bbh + bo);
        cpa16(sb + 30720u + so, Bbl + bo);
    }
}

// ---------------- GEMM: C[M,N] = A @ B^T, A/B split-bf16 K-major ---------------
// EPI: 0 none, 1 +bias, 2 gelu(+bias), 3 gelu(+bias)+res, 4 gelu(+bias)+transposed store
// OUT: 0 fp32 C, 1 split-bf16 (Ch, Cl)
template<int EPI, int OUT>
__global__ void __launch_bounds__(256, 1)
gemm_mma(const __nv_bfloat16* __restrict__ Ah, const __nv_bfloat16* __restrict__ Al,
         const __nv_bfloat16* __restrict__ Bh, const __nv_bfloat16* __restrict__ Bl,
         const float* __restrict__ bias, const float* __restrict__ res,
         float* __restrict__ Cf, __nv_bfloat16* __restrict__ Ch, __nv_bfloat16* __restrict__ Cl,
         int K, int N, long long sA, long long sB, long long sC)
{
    extern __shared__ char smc[];
    const uint32_t sbase = smem_u32(smc);
    const int tid = threadIdx.x, lane = tid & 31, wid = tid >> 5;
    const int warp_m = wid & 1, warp_n = wid >> 1;
    const long long m0 = (long long)blockIdx.y * 128;
    const long long n0 = (long long)blockIdx.x * 128;
    const long long zb = blockIdx.z;

    const __nv_bfloat16* Abh = Ah + zb * sA;  const __nv_bfloat16* Abl = Al + zb * sA;
    const __nv_bfloat16* Bbh = Bh + zb * sB;  const __nv_bfloat16* Bbl = Bl + zb * sB;

    const int NC = K >> 5;
    fill_stage(sbase,          Abh, Abl, Bbh, Bbl, m0, n0,  0, K, tid);
    asm volatile("cp.async.commit_group;" ::: "memory");
    fill_stage(sbase + STG,    Abh, Abl, Bbh, Bbl, m0, n0, 32, K, tid);
    asm volatile("cp.async.commit_group;" ::: "memory");
    fill_stage(sbase + 2*STG,  Abh, Abl, Bbh, Bbl, m0, n0, 64, K, tid);
    asm volatile("cp.async.commit_group;" ::: "memory");

    float acc[4][4][4];
    #pragma unroll
    for (int i = 0; i < 4; i++)
        #pragma unroll
        for (int j = 0; j < 4; j++)
            #pragma unroll
            for (int q = 0; q < 4; q++) acc[i][j][q] = 0.0f;

    for (int c = 0; c < NC; c++) {
        asm volatile("cp.async.wait_group 2;" ::: "memory");
        __syncthreads();
        const uint32_t sb = sbase + (uint32_t)(c % 3) * STG;

        #pragma unroll
        for (int ks = 0; ks < 2; ks++) {
            uint32_t afh[4][4], afl[4][4], bfh[2][4], bfl[2][4];
            const uint32_t abase = sb + (uint32_t)((warp_m*64 + (lane & 15)) * 80
                                   + ks*32 + ((lane >> 4) << 4));
            #pragma unroll
            for (int mt = 0; mt < 4; mt++) {
                ldsm4(afh[mt], abase + mt*1280u);
                ldsm4(afl[mt], abase + mt*1280u + 10240u);
            }
            const uint32_t bbase = sb + 20480u
                + (uint32_t)((warp_n*32 + ((lane >> 4) << 3) + (lane & 7)) * 80
                             + ks*32 + (((lane >> 3) & 1) << 4));
            #pragma unroll
            for (int nt = 0; nt < 2; nt++) {
                ldsm4(bfh[nt], bbase + nt*1280u);
                ldsm4(bfl[nt], bbase + nt*1280u + 10240u);
            }
            #pragma unroll
            for (int mt = 0; mt < 4; mt++)
                #pragma unroll
                for (int nt = 0; nt < 4; nt++) {
                    const uint32_t* bh = &bfh[nt >> 1][(nt & 1) * 2];
                    const uint32_t* bl = &bfl[nt >> 1][(nt & 1) * 2];
                    mma16816(acc[mt][nt], afh[mt], bh);
                    mma16816(acc[mt][nt], afh[mt], bl);
                    mma16816(acc[mt][nt], afl[mt], bh);
                }
        }
        __syncthreads();
        if (c + 3 < NC)
            fill_stage(sb, Abh, Abl, Bbh, Bbl, m0, n0, (c + 3) * 32, K, tid);
        asm volatile("cp.async.commit_group;" ::: "memory");
    }

    // ---------------- epilogue ----------------------------------------------------
    const int r0 = lane >> 2, c0 = (lane & 3) * 2;
    if (EPI != 4) {
        float*         Cbf = Cf + zb * sC;
        __nv_bfloat16* Cbh = Ch + zb * sC;
        __nv_bfloat16* Cbl = Cl + zb * sC;
        const float*   Rb  = res + zb * sC;
        #pragma unroll
        for (int mt = 0; mt < 4; mt++)
            #pragma unroll
            for (int nt = 0; nt < 4; nt++) {
                const int n = warp_n*32 + nt*8 + c0;
                float2 bv = make_float2(0.f, 0.f);
                if (EPI >= 1) bv = *(const float2*)&bias[n0 + n];
                #pragma unroll
                for (int hh = 0; hh < 2; hh++) {
                    const int m = warp_m*64 + mt*16 + r0 + hh*8;
                    float v0 = acc[mt][nt][hh*2], v1 = acc[mt][nt][hh*2+1];
                    if (EPI >= 1) { v0 += bv.x; v1 += bv.y; }
                    if (EPI >= 2) { v0 = gelu_f(v0); v1 = gelu_f(v1); }
                    const long long idx = (m0 + m) * (long long)N + n0 + n;
                    if (EPI == 3) {
                        float2 rv = *(const float2*)&Rb[idx];
                        v0 += rv.x; v1 += rv.y;
                    }
                    if (OUT == 0) {
                        *(float2*)&Cbf[idx] = make_float2(v0, v1);
                    } else {
                        __nv_bfloat162 h, l; split2(v0, v1, h, l);
                        *(__nv_bfloat162*)&Cbh[idx] = h;
                        *(__nv_bfloat162*)&Cbl[idx] = l;
                    }
                }
            }
    } else {
        // bias+gelu, then transposed split store: bodyT[b][n][t]
        __syncthreads();
        float* st = (float*)smc;                  // 128 x 128, stride 132
        #pragma unroll
        for (int mt = 0; mt < 4; mt++)
            #pragma unroll
            for (int nt = 0; nt < 4; nt++) {
                const int n = warp_n*32 + nt*8 + c0;
                const float2 bv = *(const float2*)&bias[n0 + n];
                #pragma unroll
                for (int hh = 0; hh < 2; hh++) {
                    const int m = warp_m*64 + mt*16 + r0 + hh*8;
                    st[m*132 + n]     = gelu_f(acc[mt][nt][hh*2]   + bv.x);
                    st[m*132 + n + 1] = gelu_f(acc[mt][nt][hh*2+1] + bv.y);
                }
            }
        __syncthreads();
        const int b  = (int)(m0 >> 11);
        const int t0 = (int)(m0 & 2047);
        for (int e = tid; e < 128 * 64; e += 256) {
            const int n  = e >> 6;
            const int tp = (e & 63) * 2;
            const float v0 = st[tp*132 + n], v1 = st[(tp+1)*132 + n];
            __nv_bfloat162 h, l; split2(v0, v1, h, l);
            const long long idx = ((long long)b * DD + n0 + n) * TT + t0 + tp;
            *(__nv_bfloat162*)&Ch[idx] = h;
            *(__nv_bfloat162*)&Cl[idx] = l;
        }
    }
}

// ---------------- fp32 -> split bf16 -------------------------------------------
__global__ void __launch_bounds__(256)
convsplit(const float* __restrict__ x, __nv_bfloat16* __restrict__ xh,
          __nv_bfloat16* __restrict__ xl, int n4)
{
    int i = blockIdx.x * 256 + threadIdx.x;
    if (i >= n4) return;
    float4 v = ((const float4*)x)[i];
    __nv_bfloat162 h0, l0, h1, l1;
    split2(v.x, v.y, h0, l0);
    split2(v.z, v.w, h1, l1);
    ((__nv_bfloat162*)xh)[i*2]   = h0;  ((__nv_bfloat162*)xh)[i*2+1] = h1;
    ((__nv_bfloat162*)xl)[i*2]   = l0;  ((__nv_bfloat162*)xl)[i*2+1] = l1;
}

// ---------------- weight transpose + split: W[K][N] -> WT hi/lo [N][K] ----------
__global__ void __launch_bounds__(256)
wtrans_split(const float* __restrict__ src, __nv_bfloat16* __restrict__ dh,
             __nv_bfloat16* __restrict__ dl, int R, int Cc)
{
    __shared__ float t[32][33];
    int x = blockIdx.x * 32 + threadIdx.x;
    int y = blockIdx.y * 32 + threadIdx.y;
    #pragma unroll
    for (int j = 0; j < 32; j += 8) t[threadIdx.y + j][threadIdx.x] = src[(long long)(y + j) * Cc + x];
    __syncthreads();
    x = blockIdx.y * 32 + threadIdx.x;
    y = blockIdx.x * 32 + threadIdx.y;
    #pragma unroll
    for (int j = 0; j < 32; j += 8) {
        float v = t[threadIdx.x][threadIdx.y + j];
        __nv_bfloat16 h = __float2bfloat16_rn(v);
        long long idx = (long long)(y + j) * R + x;
        dh[idx] = h;
        dl[idx] = __float2bfloat16_rn(v - __bfloat162float(h));
    }
}

// ---------------- softmax rows of 2048 -> split bf16 ----------------------------
__global__ void __launch_bounds__(256)
softmax2048s(const float* __restrict__ S, __nv_bfloat16* __restrict__ Sh,
             __nv_bfloat16* __restrict__ Sl)
{
    __shared__ float sh[8];
    const long long base = (long long)blockIdx.x * TT;
    const float* p = S + base;
    const int tid = threadIdx.x, lane = tid & 31, warp = tid >> 5;
    float4 x0 = *(const float4*)(p + tid * 8);
    float4 x1 = *(const float4*)(p + tid * 8 + 4);
    float x[8] = {x0.x,x0.y,x0.z,x0.w,x1.x,x1.y,x1.z,x1.w};
    float m = x[0];
    #pragma unroll
    for (int i = 1; i < 8; i++) m = fmaxf(m, x[i]);
    #pragma unroll
    for (int o = 16; o > 0; o >>= 1) m = fmaxf(m, __shfl_xor_sync(0xffffffffu, m, o));
    if (lane == 0) sh[warp] = m;
    __syncthreads();
    if (tid == 0) { float mm = sh[0]; for (int w = 1; w < 8; w++) mm = fmaxf(mm, sh[w]); sh[0] = mm; }
    __syncthreads();
    const float rmax = sh[0];
    __syncthreads();
    float e[8], s = 0.0f;
    #pragma unroll
    for (int i = 0; i < 8; i++) { e[i] = __expf(x[i] - rmax); s += e[i]; }
    #pragma unroll
    for (int o = 16; o > 0; o >>= 1) s += __shfl_xor_sync(0xffffffffu, s, o);
    if (lane == 0) sh[warp] = s;
    __syncthreads();
    if (tid == 0) { float ss = 0; for (int w = 0; w < 8; w++) ss += sh[w]; sh[0] = ss; }
    __syncthreads();
    const float inv = 1.0f / sh[0];
    #pragma unroll
    for (int i = 0; i < 4; i++) {
        __nv_bfloat162 h, l;
        split2(e[i*2] * inv, e[i*2+1] * inv, h, l);
        *(__nv_bfloat162*)&Sh[base + tid*8 + i*2] = h;
        *(__nv_bfloat162*)&Sl[base + tid*8 + i*2] = l;
    }
}

// ---------------- layernorm rows of 512 -> fp32 + split -------------------------
__global__ void __launch_bounds__(128)
layernorm512s(const float* __restrict__ X, float* __restrict__ Y,
              __nv_bfloat16* __restrict__ Yh, __nv_bfloat16* __restrict__ Yl,
              const float* __restrict__ g, const float* __restrict__ b)
{
    __shared__ float shs[4], shq[4];
    const long long base = (long long)blockIdx.x * DD;
    const float* x = X + base;
    const int tid = threadIdx.x, lane = tid & 31, warp = tid >> 5;
    float4 v = *(const float4*)(x + tid * 4);
    float s = v.x + v.y + v.z + v.w;
    float q = v.x*v.x + v.y*v.y + v.z*v.z + v.w*v.w;
    #pragma unroll
    for (int o = 16; o > 0; o >>= 1) {
        s += __shfl_xor_sync(0xffffffffu, s, o);
        q += __shfl_xor_sync(0xffffffffu, q, o);
    }
    if (lane == 0) { shs[warp] = s; shq[warp] = q; }
    __syncthreads();
    if (tid == 0) { shs[0] = shs[0]+shs[1]+shs[2]+shs[3]; shq[0] = shq[0]+shq[1]+shq[2]+shq[3]; }
    __syncthreads();
    const float mu  = shs[0] * (1.0f / DD);
    const float var = shq[0] * (1.0f / DD) - mu * mu;
    const float r = rsqrtf(var + 1e-5f);
    float4 gg = *(const float4*)(g + tid * 4);
    float4 bb = *(const float4*)(b + tid * 4);
    float4 o;
    o.x = (v.x - mu) * r * gg.x + bb.x;
    o.y = (v.y - mu) * r * gg.y + bb.y;
    o.z = (v.z - mu) * r * gg.z + bb.z;
    o.w = (v.w - mu) * r * gg.w + bb.w;
    *(float4*)(Y + base + tid * 4) = o;
    __nv_bfloat162 h0, l0, h1, l1;
    split2(o.x, o.y, h0, l0);
    split2(o.z, o.w, h1, l1);
    *(__nv_bfloat162*)&Yh[base + tid*4]     = h0;
    *(__nv_bfloat162*)&Yh[base + tid*4 + 2] = h1;
    *(__nv_bfloat162*)&Yl[base + tid*4]     = l0;
    *(__nv_bfloat162*)&Yl[base + tid*4 + 2] = l1;
}

// ---------------- launch ----------------------------------------------------------
extern "C" void kernel_launch(void* const* d_in, const int* in_sizes, int n_in,
                              void* d_out, int out_size)
{
    const float* left  = (const float*)d_in[0];
    const float* right = (const float*)d_in[1];
    const float* body  = (const float*)d_in[2];
    const float* Wl = (const float*)d_in[3];  const float* bl = (const float*)d_in[4];
    const float* Wr = (const float*)d_in[5];  const float* br = (const float*)d_in[6];
    const float* Wb = (const float*)d_in[7];  const float* bbv = (const float*)d_in[8];
    const float* Wo = (const float*)d_in[9];  const float* bo = (const float*)d_in[10];
    const float* ln_g = (const float*)d_in[11]; const float* ln_b = (const float*)d_in[12];
    const float* W1 = (const float*)d_in[13]; const float* b1 = (const float*)d_in[14];
    const float* lg2 = (const float*)d_in[15]; const float* lb2 = (const float*)d_in[16];
    const float* W2 = (const float*)d_in[17]; const float* b2 = (const float*)d_in[18];
    const float* W3 = (const float*)d_in[19]; const float* b3 = (const float*)d_in[20];
    float* out = (float*)d_out;

    float *S, *t2, *ln1;
    __nv_bfloat16 *Sh, *Sl, *eh, *el, *loh, *lol, *roh, *rol, *bth, *btl;
    __nv_bfloat16 *t1h, *t1l, *l1h, *l1l, *l2h, *l2l, *mh, *ml;
    __nv_bfloat16 *WlTh,*WlTl,*WrTh,*WrTl,*WbTh,*WbTl,*WoTh,*WoTl,*W1Th,*W1Tl,*W2Th,*W2Tl,*W3Th,*W3Tl;
    cudaGetSymbolAddress((void**)&S,   g_S);
    cudaGetSymbolAddress((void**)&Sh,  g_Sh);  cudaGetSymbolAddress((void**)&Sl,  g_Sl);
    cudaGetSymbolAddress((void**)&eh,  g_eh);  cudaGetSymbolAddress((void**)&el,  g_el);
    cudaGetSymbolAddress((void**)&loh, g_loh); cudaGetSymbolAddress((void**)&lol, g_lol);
    cudaGetSymbolAddress((void**)&roh, g_roh); cudaGetSymbolAddress((void**)&rol, g_rol);
    cudaGetSymbolAddress((void**)&bth, g_bth); cudaGetSymbolAddress((void**)&btl, g_btl);
    cudaGetSymbolAddress((void**)&t1h, g_t1h); cudaGetSymbolAddress((void**)&t1l, g_t1l);
    cudaGetSymbolAddress((void**)&t2,  g_t2);  cudaGetSymbolAddress((void**)&ln1, g_ln1);
    cudaGetSymbolAddress((void**)&l1h, g_l1h); cudaGetSymbolAddress((void**)&l1l, g_l1l);
    cudaGetSymbolAddress((void**)&l2h, g_l2h); cudaGetSymbolAddress((void**)&l2l, g_l2l);
    cudaGetSymbolAddress((void**)&mh,  g_mh);  cudaGetSymbolAddress((void**)&ml,  g_ml);
    cudaGetSymbolAddress((void**)&WlTh,g_WlTh);cudaGetSymbolAddress((void**)&WlTl,g_WlTl);
    cudaGetSymbolAddress((void**)&WrTh,g_WrTh);cudaGetSymbolAddress((void**)&WrTl,g_WrTl);
    cudaGetSymbolAddress((void**)&WbTh,g_WbTh);cudaGetSymbolAddress((void**)&WbTl,g_WbTl);
    cudaGetSymbolAddress((void**)&WoTh,g_WoTh);cudaGetSymbolAddress((void**)&WoTl,g_WoTl);
    cudaGetSymbolAddress((void**)&W1Th,g_W1Th);cudaGetSymbolAddress((void**)&W1Tl,g_W1Tl);
    cudaGetSymbolAddress((void**)&W2Th,g_W2Th);cudaGetSymbolAddress((void**)&W2Tl,g_W2Tl);
    cudaGetSymbolAddress((void**)&W3Th,g_W3Th);cudaGetSymbolAddress((void**)&W3Tl,g_W3Tl);

    cudaFuncSetAttribute(gemm_mma<0,0>, cudaFuncAttributeMaxDynamicSharedMemorySize, SMEM_BYTES);
    cudaFuncSetAttribute(gemm_mma<0,1>, cudaFuncAttributeMaxDynamicSharedMemorySize, SMEM_BYTES);
    cudaFuncSetAttribute(gemm_mma<1,0>, cudaFuncAttributeMaxDynamicSharedMemorySize, SMEM_BYTES);
    cudaFuncSetAttribute(gemm_mma<2,1>, cudaFuncAttributeMaxDynamicSharedMemorySize, SMEM_BYTES);
    cudaFuncSetAttribute(gemm_mma<3,0>, cudaFuncAttributeMaxDynamicSharedMemorySize, SMEM_BYTES);
    cudaFuncSetAttribute(gemm_mma<4,1>, cudaFuncAttributeMaxDynamicSharedMemorySize, SMEM_BYTES);

    const long long sTD = (long long)TT * DD;
    const long long sTT = (long long)TT * TT;
    dim3 tb(32, 8);
    const int n4 = BT * DD / 4;

    // weights: transpose + split
    wtrans_split<<<dim3(16,16), tb>>>(Wl, WlTh, WlTl, DD, DD);
    wtrans_split<<<dim3(16,16), tb>>>(Wr, WrTh, WrTl, DD, DD);
    wtrans_split<<<dim3(16,16), tb>>>(Wb, WbTh, WbTl, DD, DD);
    wtrans_split<<<dim3(16,16), tb>>>(Wo, WoTh, WoTl, DD, DD);
    wtrans_split<<<dim3(16,16), tb>>>(W1, W1Th, W1Tl, DD, DD);
    wtrans_split<<<dim3(48,16), tb>>>(W2, W2Th, W2Tl, DD, DMID);
    wtrans_split<<<dim3(16,48), tb>>>(W3, W3Th, W3Tl, DMID, DD);

    // projections (+GELU), split outputs
    convsplit<<<n4/256, 256>>>(left, eh, el, n4);
    gemm_mma<2,1><<<dim3(4,128,1), 256, SMEM_BYTES>>>(eh, el, WlTh, WlTl, bl, nullptr,
        nullptr, loh, lol, DD, DD, 0, 0, 0);
    convsplit<<<n4/256, 256>>>(right, eh, el, n4);
    gemm_mma<2,1><<<dim3(4,128,1), 256, SMEM_BYTES>>>(eh, el, WrTh, WrTl, br, nullptr,
        nullptr, roh, rol, DD, DD, 0, 0, 0);
    convsplit<<<n4/256, 256>>>(body, eh, el, n4);
    gemm_mma<4,1><<<dim3(4,128,1), 256, SMEM_BYTES>>>(eh, el, WbTh, WbTl, bbv, nullptr,
        nullptr, bth, btl, DD, DD, 0, 0, 0);

    // attention: S = ro @ lo^T ; softmax ; fuse = P @ bodyT^T
    gemm_mma<0,0><<<dim3(16,16,BB), 256, SMEM_BYTES>>>(roh, rol, loh, lol, nullptr, nullptr,
        S, nullptr, nullptr, DD, TT, sTD, sTD, sTT);
    softmax2048s<<<BT, 256>>>(S, Sh, Sl);
    gemm_mma<0,1><<<dim3(4,16,BB), 256, SMEM_BYTES>>>(Sh, Sl, bth, btl, nullptr, nullptr,
        nullptr, t1h, t1l, TT, DD, sTT, sTD, sTD);

    // output projection + LN
    gemm_mma<1,0><<<dim3(4,128,1), 256, SMEM_BYTES>>>(t1h, t1l, WoTh, WoTl, bo, nullptr,
        t2, nullptr, nullptr, DD, DD, 0, 0, 0);
    layernorm512s<<<BT, 128>>>(t2, ln1, l1h, l1l, ln_g, ln_b);

    // inverted residual
    gemm_mma<3,0><<<dim3(4,128,1), 256, SMEM_BYTES>>>(l1h, l1l, W1Th, W1Tl, b1, ln1,
        t2, nullptr, nullptr, DD, DD, 0, 0, 0);
    layernorm512s<<<BT, 128>>>(t2, ln1, l2h, l2l, lg2, lb2);
    gemm_mma<2,1><<<dim3(12,128,1), 256, SMEM_BYTES>>>(l2h, l2l, W2Th, W2Tl, b2, nullptr,
        nullptr, mh, ml, DD, DMID, 0, 0, 0);
    gemm_mma<1,0><<<dim3(4,128,1), 256, SMEM_BYTES>>>(mh, ml, W3Th, W3Tl, b3, nullptr,
        out, nullptr, nullptr, DMID, DD, 0, 0, 0);
}

// round 4
// speedup vs baseline: 2.0852x; 1.0276x over previous
#include <cuda_runtime.h>
#include <cuda_bf16.h>
#include <cstdint>
#include <math.h>

#define BB   8
#define TT   2048
#define DD   512
#define BT   (BB*TT)
#define DMID (3*DD)

// ---------------- scratch -------------------------------------------------------
__device__ __align__(16) __nv_bfloat16 g_Sh[(long long)BB*TT*TT];
__device__ __align__(16) __nv_bfloat16 g_Sl[(long long)BB*TT*TT];
__device__ __align__(16) __nv_bfloat16 g_eh[BT*DD],  g_el[BT*DD];
__device__ __align__(16) __nv_bfloat16 g_loh[BT*DD], g_lol[BT*DD];
__device__ __align__(16) __nv_bfloat16 g_roh[BT*DD], g_rol[BT*DD];
__device__ __align__(16) __nv_bfloat16 g_bth[BT*DD], g_btl[BT*DD];
__device__ __align__(16) __nv_bfloat16 g_t1h[BT*DD], g_t1l[BT*DD];
__device__ __align__(16) float g_t2 [BT*DD];
__device__ __align__(16) float g_ln1[BT*DD];
__device__ __align__(16) __nv_bfloat16 g_l1h[BT*DD], g_l1l[BT*DD];
__device__ __align__(16) __nv_bfloat16 g_l2h[BT*DD], g_l2l[BT*DD];
__device__ __align__(16) __nv_bfloat16 g_mh[BT*DMID], g_ml[BT*DMID];
__device__ __align__(16) __nv_bfloat16 g_WlTh[DD*DD],  g_WlTl[DD*DD];
__device__ __align__(16) __nv_bfloat16 g_WrTh[DD*DD],  g_WrTl[DD*DD];
__device__ __align__(16) __nv_bfloat16 g_WbTh[DD*DD],  g_WbTl[DD*DD];
__device__ __align__(16) __nv_bfloat16 g_WoTh[DD*DD],  g_WoTl[DD*DD];
__device__ __align__(16) __nv_bfloat16 g_W1Th[DD*DD],  g_W1Tl[DD*DD];
__device__ __align__(16) __nv_bfloat16 g_W2Th[DMID*DD],g_W2Tl[DMID*DD];
__device__ __align__(16) __nv_bfloat16 g_W3Th[DD*DMID],g_W3Tl[DD*DMID];

// ---------------- helpers -------------------------------------------------------
__device__ __forceinline__ float gelu_f(float x) {
    return 0.5f * x * (1.0f + erff(x * 0.7071067811865476f));
}
__device__ __forceinline__ uint32_t smem_u32(const void* p) {
    uint32_t a;
    asm("{ .reg .u64 t; cvta.to.shared.u64 t, %1; cvt.u32.u64 %0, t; }" : "=r"(a) : "l"(p));
    return a;
}
__device__ __forceinline__ void cpa16(uint32_t dst, const void* src) {
    asm volatile("cp.async.cg.shared.global [%0], [%1], 16;" :: "r"(dst), "l"(src));
}
__device__ __forceinline__ void ldsm4(uint32_t* r, uint32_t a) {
    asm volatile("ldmatrix.sync.aligned.m8n8.x4.shared.b16 {%0,%1,%2,%3}, [%4];"
                 : "=r"(r[0]), "=r"(r[1]), "=r"(r[2]), "=r"(r[3]) : "r"(a));
}
__device__ __forceinline__ void mma16816(float* d, const uint32_t* a, const uint32_t* b) {
    asm volatile("mma.sync.aligned.m16n8k16.row.col.f32.bf16.bf16.f32 "
                 "{%0,%1,%2,%3}, {%4,%5,%6,%7}, {%8,%9}, {%0,%1,%2,%3};"
                 : "+f"(d[0]), "+f"(d[1]), "+f"(d[2]), "+f"(d[3])
                 : "r"(a[0]), "r"(a[1]), "r"(a[2]), "r"(a[3]), "r"(b[0]), "r"(b[1]));
}
__device__ __forceinline__ void split2(float v0, float v1, __nv_bfloat162& h, __nv_bfloat162& l) {
    h = __floats2bfloat162_rn(v0, v1);
    float2 f = __bfloat1622float2(h);
    l = __floats2bfloat162_rn(v0 - f.x, v1 - f.y);
}

#define STG 40960u            // stage bytes: Ah 10240 | Al 10240 | Bh 10240 | Bl 10240
#define SMEM_BYTES (4*40960)  // 4-stage pipeline

// fill one 128x32(k) chunk of A and B (all 4 split arrays) via cp.async
__device__ __forceinline__ void fill_stage(uint32_t sb,
    const __nv_bfloat16* Abh, const __nv_bfloat16* Abl,
    const __nv_bfloat16* Bbh, const __nv_bfloat16* Bbl,
    long long m0, long long n0, int k0, int K, int tid)
{
    #pragma unroll
    for (int j = 0; j < 2; j++) {
        const int id  = tid * 2 + j;          // 0..511
        const int row = id >> 2, ch = id & 3;
        const uint32_t so = (uint32_t)(row * 80 + ch * 16);
        const long long ao = (m0 + row) * (long long)K + k0 + ch * 8;
        const long long bo = (n0 + row) * (long long)K + k0 + ch * 8;
        cpa16(sb +          so, Abh + ao);
        cpa16(sb + 10240u + so, Abl + ao);
        cpa16(sb + 20480u + so, Bbh + bo);
        cpa16(sb + 30720u + so, Bbl + bo);
    }
}

// ---------------- GEMM: C[M,N] = A @ B^T, A/B split-bf16 K-major ---------------
// EPI: 0 none, 1 +bias, 2 gelu(+bias), 3 gelu(+bias)+res, 4 gelu(+bias)+transposed store
// OUT: 0 fp32 C, 1 split-bf16 (Ch, Cl)
template<int EPI, int OUT>
__global__ void __launch_bounds__(256, 1)
gemm_mma(const __nv_bfloat16* __restrict__ Ah, const __nv_bfloat16* __restrict__ Al,
         const __nv_bfloat16* __restrict__ Bh, const __nv_bfloat16* __restrict__ Bl,
         const float* __restrict__ bias, const float* __restrict__ res,
         float* __restrict__ Cf, __nv_bfloat16* __restrict__ Ch, __nv_bfloat16* __restrict__ Cl,
         int K, int N, long long sA, long long sB, long long sC)
{
    extern __shared__ char smc[];
    const uint32_t sbase = smem_u32(smc);
    const int tid = threadIdx.x, lane = tid & 31, wid = tid >> 5;
    const int warp_m = wid & 1, warp_n = wid >> 1;
    const long long m0 = (long long)blockIdx.y * 128;
    const long long n0 = (long long)blockIdx.x * 128;
    const long long zb = blockIdx.z;

    const __nv_bfloat16* Abh = Ah + zb * sA;  const __nv_bfloat16* Abl = Al + zb * sA;
    const __nv_bfloat16* Bbh = Bh + zb * sB;  const __nv_bfloat16* Bbl = Bl + zb * sB;

    const int NC = K >> 5;
    fill_stage(sbase,          Abh, Abl, Bbh, Bbl, m0, n0,  0, K, tid);
    asm volatile("cp.async.commit_group;" ::: "memory");
    fill_stage(sbase + STG,    Abh, Abl, Bbh, Bbl, m0, n0, 32, K, tid);
    asm volatile("cp.async.commit_group;" ::: "memory");
    fill_stage(sbase + 2*STG,  Abh, Abl, Bbh, Bbl, m0, n0, 64, K, tid);
    asm volatile("cp.async.commit_group;" ::: "memory");

    float acc[4][4][4];
    #pragma unroll
    for (int i = 0; i < 4; i++)
        #pragma unroll
        for (int j = 0; j < 4; j++)
            #pragma unroll
            for (int q = 0; q < 4; q++) acc[i][j][q] = 0.0f;

    const uint32_t a_off = (uint32_t)((warp_m*64 + (lane & 15)) * 80 + ((lane >> 4) << 4));
    const uint32_t b_off = 20480u
        + (uint32_t)((warp_n*32 + ((lane >> 4) << 3) + (lane & 7)) * 80
                     + (((lane >> 3) & 1) << 4));

    for (int c = 0; c < NC; c++) {
        asm volatile("cp.async.wait_group 2;" ::: "memory");
        __syncthreads();
        const uint32_t sb = sbase + (uint32_t)(c & 3) * STG;

        // refill slot (c+3)%4 (= slot (c-1)%4, retired by the barrier above)
        if (c + 3 < NC)
            fill_stage(sbase + (uint32_t)((c + 3) & 3) * STG,
                       Abh, Abl, Bbh, Bbl, m0, n0, (c + 3) * 32, K, tid);
        asm volatile("cp.async.commit_group;" ::: "memory");

        // preload ALL fragments for this chunk (both k-slices), then run MMAs
        uint32_t afh[2][4][4], afl[2][4][4], bfh[2][2][4], bfl[2][2][4];
        #pragma unroll
        for (int ks = 0; ks < 2; ks++) {
            const uint32_t abase = sb + a_off + (uint32_t)(ks*32);
            #pragma unroll
            for (int mt = 0; mt < 4; mt++) {
                ldsm4(afh[ks][mt], abase + mt*1280u);
                ldsm4(afl[ks][mt], abase + mt*1280u + 10240u);
            }
            const uint32_t bbase = sb + b_off + (uint32_t)(ks*32);
            #pragma unroll
            for (int nt = 0; nt < 2; nt++) {
                ldsm4(bfh[ks][nt], bbase + nt*1280u);
                ldsm4(bfl[ks][nt], bbase + nt*1280u + 10240u);
            }
        }
        #pragma unroll
        for (int ks = 0; ks < 2; ks++)
            #pragma unroll
            for (int mt = 0; mt < 4; mt++)
                #pragma unroll
                for (int nt = 0; nt < 4; nt++) {
                    const uint32_t* bh = &bfh[ks][nt >> 1][(nt & 1) * 2];
                    const uint32_t* bl = &bfl[ks][nt >> 1][(nt & 1) * 2];
                    mma16816(acc[mt][nt], afh[ks][mt], bh);
                    mma16816(acc[mt][nt], afh[ks][mt], bl);
                    mma16816(acc[mt][nt], afl[ks][mt], bh);
                }
    }

    // ---------------- epilogue ----------------------------------------------------
    const int r0 = lane >> 2, c0 = (lane & 3) * 2;
    if (EPI != 4) {
        float*         Cbf = Cf + zb * sC;
        __nv_bfloat16* Cbh = Ch + zb * sC;
        __nv_bfloat16* Cbl = Cl + zb * sC;
        const float*   Rb  = res + zb * sC;
        #pragma unroll
        for (int mt = 0; mt < 4; mt++)
            #pragma unroll
            for (int nt = 0; nt < 4; nt++) {
                const int n = warp_n*32 + nt*8 + c0;
                float2 bv = make_float2(0.f, 0.f);
                if (EPI >= 1) bv = *(const float2*)&bias[n0 + n];
                #pragma unroll
                for (int hh = 0; hh < 2; hh++) {
                    const int m = warp_m*64 + mt*16 + r0 + hh*8;
                    float v0 = acc[mt][nt][hh*2], v1 = acc[mt][nt][hh*2+1];
                    if (EPI >= 1) { v0 += bv.x; v1 += bv.y; }
                    if (EPI >= 2) { v0 = gelu_f(v0); v1 = gelu_f(v1); }
                    const long long idx = (m0 + m) * (long long)N + n0 + n;
                    if (EPI == 3) {
                        float2 rv = *(const float2*)&Rb[idx];
                        v0 += rv.x; v1 += rv.y;
                    }
                    if (OUT == 0) {
                        *(float2*)&Cbf[idx] = make_float2(v0, v1);
                    } else {
                        __nv_bfloat162 h, l; split2(v0, v1, h, l);
                        *(__nv_bfloat162*)&Cbh[idx] = h;
                        *(__nv_bfloat162*)&Cbl[idx] = l;
                    }
                }
            }
    } else {
        // bias+gelu, then transposed split store: bodyT[b][n][t]
        __syncthreads();
        float* st = (float*)smc;                  // 128 x 128, stride 132
        #pragma unroll
        for (int mt = 0; mt < 4; mt++)
            #pragma unroll
            for (int nt = 0; nt < 4; nt++) {
                const int n = warp_n*32 + nt*8 + c0;
                const float2 bv = *(const float2*)&bias[n0 + n];
                #pragma unroll
                for (int hh = 0; hh < 2; hh++) {
                    const int m = warp_m*64 + mt*16 + r0 + hh*8;
                    st[m*132 + n]     = gelu_f(acc[mt][nt][hh*2]   + bv.x);
                    st[m*132 + n + 1] = gelu_f(acc[mt][nt][hh*2+1] + bv.y);
                }
            }
        __syncthreads();
        const int b  = (int)(m0 >> 11);
        const int t0 = (int)(m0 & 2047);
        for (int e = tid; e < 128 * 64; e += 256) {
            const int n  = e >> 6;
            const int tp = (e & 63) * 2;
            const float v0 = st[tp*132 + n], v1 = st[(tp+1)*132 + n];
            __nv_bfloat162 h, l; split2(v0, v1, h, l);
            const long long idx = ((long long)b * DD + n0 + n) * TT + t0 + tp;
            *(__nv_bfloat162*)&Ch[idx] = h;
            *(__nv_bfloat162*)&Cl[idx] = l;
        }
    }
}

// ---------------- fp32 -> split bf16 -------------------------------------------
__global__ void __launch_bounds__(256)
convsplit(const float* __restrict__ x, __nv_bfloat16* __restrict__ xh,
          __nv_bfloat16* __restrict__ xl, int n4)
{
    int i = blockIdx.x * 256 + threadIdx.x;
    if (i >= n4) return;
    float4 v = ((const float4*)x)[i];
    __nv_bfloat162 h0, l0, h1, l1;
    split2(v.x, v.y, h0, l0);
    split2(v.z, v.w, h1, l1);
    ((__nv_bfloat162*)xh)[i*2]   = h0;  ((__nv_bfloat162*)xh)[i*2+1] = h1;
    ((__nv_bfloat162*)xl)[i*2]   = l0;  ((__nv_bfloat162*)xl)[i*2+1] = l1;
}

// ---------------- weight transpose + split: W[K][N] -> WT hi/lo [N][K] ----------
__global__ void __launch_bounds__(256)
wtrans_split(const float* __restrict__ src, __nv_bfloat16* __restrict__ dh,
             __nv_bfloat16* __restrict__ dl, int R, int Cc)
{
    __shared__ float t[32][33];
    int x = blockIdx.x * 32 + threadIdx.x;
    int y = blockIdx.y * 32 + threadIdx.y;
    #pragma unroll
    for (int j = 0; j < 32; j += 8) t[threadIdx.y + j][threadIdx.x] = src[(long long)(y + j) * Cc + x];
    __syncthreads();
    x = blockIdx.y * 32 + threadIdx.x;
    y = blockIdx.x * 32 + threadIdx.y;
    #pragma unroll
    for (int j = 0; j < 32; j += 8) {
        float v = t[threadIdx.x][threadIdx.y + j];
        __nv_bfloat16 h = __float2bfloat16_rn(v);
        long long idx = (long long)(y + j) * R + x;
        dh[idx] = h;
        dl[idx] = __float2bfloat16_rn(v - __bfloat162float(h));
    }
}

// ---------------- softmax rows of 2048, split-bf16 in/out ------------------------
__global__ void __launch_bounds__(256)
softmax2048s(__nv_bfloat16* __restrict__ Sh, __nv_bfloat16* __restrict__ Sl)
{
    __shared__ float sh[8];
    const long long base = (long long)blockIdx.x * TT;
    const int tid = threadIdx.x, lane = tid & 31, warp = tid >> 5;

    // reconstruct x = hi + lo (exact to 2^-18)
    float x[8];
    {
        uint4 hv = *(const uint4*)(Sh + base + tid * 8);
        uint4 lv = *(const uint4*)(Sl + base + tid * 8);
        const uint32_t hr[4] = {hv.x, hv.y, hv.z, hv.w};
        const uint32_t lr[4] = {lv.x, lv.y, lv.z, lv.w};
        #pragma unroll
        for (int i = 0; i < 4; i++) {
            float2 h2 = __bfloat1622float2(*(const __nv_bfloat162*)&hr[i]);
            float2 l2 = __bfloat1622float2(*(const __nv_bfloat162*)&lr[i]);
            x[i*2]   = h2.x + l2.x;
            x[i*2+1] = h2.y + l2.y;
        }
    }
    float m = x[0];
    #pragma unroll
    for (int i = 1; i < 8; i++) m = fmaxf(m, x[i]);
    #pragma unroll
    for (int o = 16; o > 0; o >>= 1) m = fmaxf(m, __shfl_xor_sync(0xffffffffu, m, o));
    if (lane == 0) sh[warp] = m;
    __syncthreads();
    if (tid == 0) { float mm = sh[0]; for (int w = 1; w < 8; w++) mm = fmaxf(mm, sh[w]); sh[0] = mm; }
    __syncthreads();
    const float rmax = sh[0];
    __syncthreads();
    float e[8], s = 0.0f;
    #pragma unroll
    for (int i = 0; i < 8; i++) { e[i] = __expf(x[i] - rmax); s += e[i]; }
    #pragma unroll
    for (int o = 16; o > 0; o >>= 1) s += __shfl_xor_sync(0xffffffffu, s, o);
    if (lane == 0) sh[warp] = s;
    __syncthreads();
    if (tid == 0) { float ss = 0; for (int w = 0; w < 8; w++) ss += sh[w]; sh[0] = ss; }
    __syncthreads();
    const float inv = 1.0f / sh[0];
    #pragma unroll
    for (int i = 0; i < 4; i++) {
        __nv_bfloat162 h, l;
        split2(e[i*2] * inv, e[i*2+1] * inv, h, l);
        *(__nv_bfloat162*)&Sh[base + tid*8 + i*2] = h;
        *(__nv_bfloat162*)&Sl[base + tid*8 + i*2] = l;
    }
}

// ---------------- layernorm rows of 512 -> fp32 + split -------------------------
__global__ void __launch_bounds__(128)
layernorm512s(const float* __restrict__ X, float* __restrict__ Y,
              __nv_bfloat16* __restrict__ Yh, __nv_bfloat16* __restrict__ Yl,
              const float* __restrict__ g, const float* __restrict__ b)
{
    __shared__ float shs[4], shq[4];
    const long long base = (long long)blockIdx.x * DD;
    const float* x = X + base;
    const int tid = threadIdx.x, lane = tid & 31, warp = tid >> 5;
    float4 v = *(const float4*)(x + tid * 4);
    float s = v.x + v.y + v.z + v.w;
    float q = v.x*v.x + v.y*v.y + v.z*v.z + v.w*v.w;
    #pragma unroll
    for (int o = 16; o > 0; o >>= 1) {
        s += __shfl_xor_sync(0xffffffffu, s, o);
        q += __shfl_xor_sync(0xffffffffu, q, o);
    }
    if (lane == 0) { shs[warp] = s; shq[warp] = q; }
    __syncthreads();
    if (tid == 0) { shs[0] = shs[0]+shs[1]+shs[2]+shs[3]; shq[0] = shq[0]+shq[1]+shq[2]+shq[3]; }
    __syncthreads();
    const float mu  = shs[0] * (1.0f / DD);
    const float var = shq[0] * (1.0f / DD) - mu * mu;
    const float r = rsqrtf(var + 1e-5f);
    float4 gg = *(const float4*)(g + tid * 4);
    float4 bb = *(const float4*)(b + tid * 4);
    float4 o;
    o.x = (v.x - mu) * r * gg.x + bb.x;
    o.y = (v.y - mu) * r * gg.y + bb.y;
    o.z = (v.z - mu) * r * gg.z + bb.z;
    o.w = (v.w - mu) * r * gg.w + bb.w;
    *(float4*)(Y + base + tid * 4) = o;
    __nv_bfloat162 h0, l0, h1, l1;
    split2(o.x, o.y, h0, l0);
    split2(o.z, o.w, h1, l1);
    *(__nv_bfloat162*)&Yh[base + tid*4]     = h0;
    *(__nv_bfloat162*)&Yh[base + tid*4 + 2] = h1;
    *(__nv_bfloat162*)&Yl[base + tid*4]     = l0;
    *(__nv_bfloat162*)&Yl[base + tid*4 + 2] = l1;
}

// ---------------- launch ----------------------------------------------------------
extern "C" void kernel_launch(void* const* d_in, const int* in_sizes, int n_in,
                              void* d_out, int out_size)
{
    const float* left  = (const float*)d_in[0];
    const float* right = (const float*)d_in[1];
    const float* body  = (const float*)d_in[2];
    const float* Wl = (const float*)d_in[3];  const float* bl = (const float*)d_in[4];
    const float* Wr = (const float*)d_in[5];  const float* br = (const float*)d_in[6];
    const float* Wb = (const float*)d_in[7];  const float* bbv = (const float*)d_in[8];
    const float* Wo = (const float*)d_in[9];  const float* bo = (const float*)d_in[10];
    const float* ln_g = (const float*)d_in[11]; const float* ln_b = (const float*)d_in[12];
    const float* W1 = (const float*)d_in[13]; const float* b1 = (const float*)d_in[14];
    const float* lg2 = (const float*)d_in[15]; const float* lb2 = (const float*)d_in[16];
    const float* W2 = (const float*)d_in[17]; const float* b2 = (const float*)d_in[18];
    const float* W3 = (const float*)d_in[19]; const float* b3 = (const float*)d_in[20];
    float* out = (float*)d_out;

    float *t2, *ln1;
    __nv_bfloat16 *Sh, *Sl, *eh, *el, *loh, *lol, *roh, *rol, *bth, *btl;
    __nv_bfloat16 *t1h, *t1l, *l1h, *l1l, *l2h, *l2l, *mh, *ml;
    __nv_bfloat16 *WlTh,*WlTl,*WrTh,*WrTl,*WbTh,*WbTl,*WoTh,*WoTl,*W1Th,*W1Tl,*W2Th,*W2Tl,*W3Th,*W3Tl;
    cudaGetSymbolAddress((void**)&Sh,  g_Sh);  cudaGetSymbolAddress((void**)&Sl,  g_Sl);
    cudaGetSymbolAddress((void**)&eh,  g_eh);  cudaGetSymbolAddress((void**)&el,  g_el);
    cudaGetSymbolAddress((void**)&loh, g_loh); cudaGetSymbolAddress((void**)&lol, g_lol);
    cudaGetSymbolAddress((void**)&roh, g_roh); cudaGetSymbolAddress((void**)&rol, g_rol);
    cudaGetSymbolAddress((void**)&bth, g_bth); cudaGetSymbolAddress((void**)&btl, g_btl);
    cudaGetSymbolAddress((void**)&t1h, g_t1h); cudaGetSymbolAddress((void**)&t1l, g_t1l);
    cudaGetSymbolAddress((void**)&t2,  g_t2);  cudaGetSymbolAddress((void**)&ln1, g_ln1);
    cudaGetSymbolAddress((void**)&l1h, g_l1h); cudaGetSymbolAddress((void**)&l1l, g_l1l);
    cudaGetSymbolAddress((void**)&l2h, g_l2h); cudaGetSymbolAddress((void**)&l2l, g_l2l);
    cudaGetSymbolAddress((void**)&mh,  g_mh);  cudaGetSymbolAddress((void**)&ml,  g_ml);
    cudaGetSymbolAddress((void**)&WlTh,g_WlTh);cudaGetSymbolAddress((void**)&WlTl,g_WlTl);
    cudaGetSymbolAddress((void**)&WrTh,g_WrTh);cudaGetSymbolAddress((void**)&WrTl,g_WrTl);
    cudaGetSymbolAddress((void**)&WbTh,g_WbTh);cudaGetSymbolAddress((void**)&WbTl,g_WbTl);
    cudaGetSymbolAddress((void**)&WoTh,g_WoTh);cudaGetSymbolAddress((void**)&WoTl,g_WoTl);
    cudaGetSymbolAddress((void**)&W1Th,g_W1Th);cudaGetSymbolAddress((void**)&W1Tl,g_W1Tl);
    cudaGetSymbolAddress((void**)&W2Th,g_W2Th);cudaGetSymbolAddress((void**)&W2Tl,g_W2Tl);
    cudaGetSymbolAddress((void**)&W3Th,g_W3Th);cudaGetSymbolAddress((void**)&W3Tl,g_W3Tl);

    cudaFuncSetAttribute(gemm_mma<0,1>, cudaFuncAttributeMaxDynamicSharedMemorySize, SMEM_BYTES);
    cudaFuncSetAttribute(gemm_mma<1,0>, cudaFuncAttributeMaxDynamicSharedMemorySize, SMEM_BYTES);
    cudaFuncSetAttribute(gemm_mma<2,1>, cudaFuncAttributeMaxDynamicSharedMemorySize, SMEM_BYTES);
    cudaFuncSetAttribute(gemm_mma<3,0>, cudaFuncAttributeMaxDynamicSharedMemorySize, SMEM_BYTES);
    cudaFuncSetAttribute(gemm_mma<4,1>, cudaFuncAttributeMaxDynamicSharedMemorySize, SMEM_BYTES);

    const long long sTD = (long long)TT * DD;
    const long long sTT = (long long)TT * TT;
    dim3 tb(32, 8);
    const int n4 = BT * DD / 4;

    // weights: transpose + split
    wtrans_split<<<dim3(16,16), tb>>>(Wl, WlTh, WlTl, DD, DD);
    wtrans_split<<<dim3(16,16), tb>>>(Wr, WrTh, WrTl, DD, DD);
    wtrans_split<<<dim3(16,16), tb>>>(Wb, WbTh, WbTl, DD, DD);
    wtrans_split<<<dim3(16,16), tb>>>(Wo, WoTh, WoTl, DD, DD);
    wtrans_split<<<dim3(16,16), tb>>>(W1, W1Th, W1Tl, DD, DD);
    wtrans_split<<<dim3(48,16), tb>>>(W2, W2Th, W2Tl, DD, DMID);
    wtrans_split<<<dim3(16,48), tb>>>(W3, W3Th, W3Tl, DMID, DD);

    // projections (+GELU), split outputs
    convsplit<<<n4/256, 256>>>(left, eh, el, n4);
    gemm_mma<2,1><<<dim3(4,128,1), 256, SMEM_BYTES>>>(eh, el, WlTh, WlTl, bl, nullptr,
        nullptr, loh, lol, DD, DD, 0, 0, 0);
    convsplit<<<n4/256, 256>>>(right, eh, el, n4);
    gemm_mma<2,1><<<dim3(4,128,1), 256, SMEM_BYTES>>>(eh, el, WrTh, WrTl, br, nullptr,
        nullptr, roh, rol, DD, DD, 0, 0, 0);
    convsplit<<<n4/256, 256>>>(body, eh, el, n4);
    gemm_mma<4,1><<<dim3(4,128,1), 256, SMEM_BYTES>>>(eh, el, WbTh, WbTl, bbv, nullptr,
        nullptr, bth, btl, DD, DD, 0, 0, 0);

    // attention: S = ro @ lo^T (split out) ; softmax in-place on split ; fuse
    gemm_mma<0,1><<<dim3(16,16,BB), 256, SMEM_BYTES>>>(roh, rol, loh, lol, nullptr, nullptr,
        nullptr, Sh, Sl, DD, TT, sTD, sTD, sTT);
    softmax2048s<<<BT, 256>>>(Sh, Sl);
    gemm_mma<0,1><<<dim3(4,16,BB), 256, SMEM_BYTES>>>(Sh, Sl, bth, btl, nullptr, nullptr,
        nullptr, t1h, t1l, TT, DD, sTT, sTD, sTD);

    // output projection + LN
    gemm_mma<1,0><<<dim3(4,128,1), 256, SMEM_BYTES>>>(t1h, t1l, WoTh, WoTl, bo, nullptr,
        t2, nullptr, nullptr, DD, DD, 0, 0, 0);
    layernorm512s<<<BT, 128>>>(t2, ln1, l1h, l1l, ln_g, ln_b);

    // inverted residual
    gemm_mma<3,0><<<dim3(4,128,1), 256, SMEM_BYTES>>>(l1h, l1l, W1Th, W1Tl, b1, ln1,
        t2, nullptr, nullptr, DD, DD, 0, 0, 0);
    layernorm512s<<<BT, 128>>>(t2, ln1, l2h, l2l, lg2, lb2);
    gemm_mma<2,1><<<dim3(12,128,1), 256, SMEM_BYTES>>>(l2h, l2l, W2Th, W2Tl, b2, nullptr,
        nullptr, mh, ml, DD, DMID, 0, 0, 0);
    gemm_mma<1,0><<<dim3(4,128,1), 256, SMEM_BYTES>>>(mh, ml, W3Th, W3Tl, b3, nullptr,
        out, nullptr, nullptr, DMID, DD, 0, 0, 0);
}

// round 5
// speedup vs baseline: 2.4960x; 1.1971x over previous
#include <cuda_runtime.h>
#include <cuda_bf16.h>
#include <cstdint>
#include <math.h>

#define BB   8
#define TT   2048
#define DD   512
#define BT   (BB*TT)
#define DMID (3*DD)

// ---------------- scratch -------------------------------------------------------
__device__ __align__(16) __nv_bfloat16 g_Sh[(long long)BB*TT*TT];
__device__ __align__(16) __nv_bfloat16 g_Sl[(long long)BB*TT*TT];
__device__ __align__(16) __nv_bfloat16 g_eh[BT*DD],  g_el[BT*DD];
__device__ __align__(16) __nv_bfloat16 g_loh[BT*DD], g_lol[BT*DD];
__device__ __align__(16) __nv_bfloat16 g_roh[BT*DD], g_rol[BT*DD];
__device__ __align__(16) __nv_bfloat16 g_bth[BT*DD], g_btl[BT*DD];
__device__ __align__(16) __nv_bfloat16 g_t1h[BT*DD], g_t1l[BT*DD];
__device__ __align__(16) float g_t2 [BT*DD];
__device__ __align__(16) float g_ln1[BT*DD];
__device__ __align__(16) __nv_bfloat16 g_l1h[BT*DD], g_l1l[BT*DD];
__device__ __align__(16) __nv_bfloat16 g_l2h[BT*DD], g_l2l[BT*DD];
__device__ __align__(16) __nv_bfloat16 g_mh[BT*DMID], g_ml[BT*DMID];
__device__ __align__(16) __nv_bfloat16 g_WlTh[DD*DD],  g_WlTl[DD*DD];
__device__ __align__(16) __nv_bfloat16 g_WrTh[DD*DD],  g_WrTl[DD*DD];
__device__ __align__(16) __nv_bfloat16 g_WbTh[DD*DD],  g_WbTl[DD*DD];
__device__ __align__(16) __nv_bfloat16 g_WoTh[DD*DD],  g_WoTl[DD*DD];
__device__ __align__(16) __nv_bfloat16 g_W1Th[DD*DD],  g_W1Tl[DD*DD];
__device__ __align__(16) __nv_bfloat16 g_W2Th[DMID*DD],g_W2Tl[DMID*DD];
__device__ __align__(16) __nv_bfloat16 g_W3Th[DD*DMID],g_W3Tl[DD*DMID];

// ---------------- helpers -------------------------------------------------------
__device__ __forceinline__ float gelu_f(float x) {
    return 0.5f * x * (1.0f + erff(x * 0.7071067811865476f));
}
__device__ __forceinline__ uint32_t smem_u32(const void* p) {
    uint32_t a;
    asm("{ .reg .u64 t; cvta.to.shared.u64 t, %1; cvt.u32.u64 %0, t; }" : "=r"(a) : "l"(p));
    return a;
}
__device__ __forceinline__ void cpa16(uint32_t dst, const void* src) {
    asm volatile("cp.async.cg.shared.global [%0], [%1], 16;" :: "r"(dst), "l"(src));
}
__device__ __forceinline__ void ldsm4(uint32_t* r, uint32_t a) {
    asm volatile("ldmatrix.sync.aligned.m8n8.x4.shared.b16 {%0,%1,%2,%3}, [%4];"
                 : "=r"(r[0]), "=r"(r[1]), "=r"(r[2]), "=r"(r[3]) : "r"(a));
}
__device__ __forceinline__ void mma16816(float* d, const uint32_t* a, const uint32_t* b) {
    asm volatile("mma.sync.aligned.m16n8k16.row.col.f32.bf16.bf16.f32 "
                 "{%0,%1,%2,%3}, {%4,%5,%6,%7}, {%8,%9}, {%0,%1,%2,%3};"
                 : "+f"(d[0]), "+f"(d[1]), "+f"(d[2]), "+f"(d[3])
                 : "r"(a[0]), "r"(a[1]), "r"(a[2]), "r"(a[3]), "r"(b[0]), "r"(b[1]));
}
__device__ __forceinline__ void split2(float v0, float v1, __nv_bfloat162& h, __nv_bfloat162& l) {
    h = __floats2bfloat162_rn(v0, v1);
    float2 f = __bfloat1622float2(h);
    l = __floats2bfloat162_rn(v0 - f.x, v1 - f.y);
}

// stage: Ah 10240 | Al 10240 | Bh 20480 | Bl 20480  = 61440 bytes
#define STG 61440u
#define SMEM_BYTES (3*61440)   // 3-stage pipeline (184320 B)

// fill one chunk: A 128 rows, B 256 rows, 32 k-cols, hi+lo, 80B row stride
__device__ __forceinline__ void fill_stage(uint32_t sb,
    const __nv_bfloat16* Abh, const __nv_bfloat16* Abl,
    const __nv_bfloat16* Bbh, const __nv_bfloat16* Bbl,
    long long m0, long long n0, int k0, int K, int tid)
{
    #pragma unroll
    for (int j = 0; j < 2; j++) {
        const int id  = j*256 + tid;             // 0..511
        const int row = id >> 2, ch = id & 3;
        const uint32_t so = (uint32_t)(row * 80 + ch * 16);
        const long long ao = (m0 + row) * (long long)K + k0 + ch * 8;
        cpa16(sb +          so, Abh + ao);
        cpa16(sb + 10240u + so, Abl + ao);
    }
    #pragma unroll
    for (int j = 0; j < 4; j++) {
        const int id  = j*256 + tid;             // 0..1023
        const int row = id >> 2, ch = id & 3;
        const uint32_t so = (uint32_t)(row * 80 + ch * 16);
        const long long bo = (n0 + row) * (long long)K + k0 + ch * 8;
        cpa16(sb + 20480u + so, Bbh + bo);
        cpa16(sb + 40960u + so, Bbl + bo);
    }
}

// ---------------- GEMM: C[M,N] tile 128x256 = A @ B^T, split-bf16 K-major -------
// EPI: 0 none, 1 +bias, 2 gelu(+bias), 3 gelu(+bias)+res, 4 gelu(+bias)+transposed
// OUT: 0 fp32 C, 1 split-bf16 (Ch, Cl)
template<int EPI, int OUT>
__global__ void __launch_bounds__(256, 1)
gemm_mma(const __nv_bfloat16* __restrict__ Ah, const __nv_bfloat16* __restrict__ Al,
         const __nv_bfloat16* __restrict__ Bh, const __nv_bfloat16* __restrict__ Bl,
         const float* __restrict__ bias, const float* __restrict__ res,
         float* __restrict__ Cf, __nv_bfloat16* __restrict__ Ch, __nv_bfloat16* __restrict__ Cl,
         int K, int N, long long sA, long long sB, long long sC)
{
    extern __shared__ char smc[];
    const uint32_t sbase = smem_u32(smc);
    const int tid = threadIdx.x, lane = tid & 31, wid = tid >> 5;
    const int warp_m = wid & 1, warp_n = wid >> 1;   // 2 x 4 warp grid, 64x64 warp tile
    const long long m0 = (long long)blockIdx.y * 128;
    const long long n0 = (long long)blockIdx.x * 256;
    const long long zb = blockIdx.z;

    const __nv_bfloat16* Abh = Ah + zb * sA;  const __nv_bfloat16* Abl = Al + zb * sA;
    const __nv_bfloat16* Bbh = Bh + zb * sB;  const __nv_bfloat16* Bbl = Bl + zb * sB;

    const int NC = K >> 5;
    fill_stage(sbase,       Abh, Abl, Bbh, Bbl, m0, n0,  0, K, tid);
    asm volatile("cp.async.commit_group;" ::: "memory");
    fill_stage(sbase + STG, Abh, Abl, Bbh, Bbl, m0, n0, 32, K, tid);
    asm volatile("cp.async.commit_group;" ::: "memory");

    float acc[4][8][4];
    #pragma unroll
    for (int i = 0; i < 4; i++)
        #pragma unroll
        for (int j = 0; j < 8; j++)
            #pragma unroll
            for (int q = 0; q < 4; q++) acc[i][j][q] = 0.0f;

    const uint32_t a_off = (uint32_t)((warp_m*64 + (lane & 15)) * 80 + ((lane >> 4) << 4));
    const uint32_t b_off = 20480u
        + (uint32_t)((warp_n*64 + ((lane >> 4) << 3) + (lane & 7)) * 80
                     + (((lane >> 3) & 1) << 4));

    for (int c = 0; c < NC; c++) {
        asm volatile("cp.async.wait_group 1;" ::: "memory");
        __syncthreads();
        const uint32_t sb = sbase + (uint32_t)(c % 3) * STG;

        // ---- k-slice 0: preload fragments ----
        uint32_t afh[4][4], afl[4][4], bfh[4][4], bfl[4][4];
        {
            const uint32_t ab = sb + a_off;
            #pragma unroll
            for (int mt = 0; mt < 4; mt++) {
                ldsm4(afh[mt], ab + mt*1280u);
                ldsm4(afl[mt], ab + mt*1280u + 10240u);
            }
            const uint32_t bb = sb + b_off;
            #pragma unroll
            for (int nt = 0; nt < 4; nt++) {
                ldsm4(bfh[nt], bb + nt*1280u);
                ldsm4(bfl[nt], bb + nt*1280u + 20480u);
            }
        }
        // refill slot (c+2)%3 (its last readers finished in iter c-1, retired by barrier)
        if (c + 2 < NC)
            fill_stage(sbase + (uint32_t)((c + 2) % 3) * STG,
                       Abh, Abl, Bbh, Bbl, m0, n0, (c + 2) * 32, K, tid);
        asm volatile("cp.async.commit_group;" ::: "memory");

        #pragma unroll
        for (int mt = 0; mt < 4; mt++)
            #pragma unroll
            for (int nt = 0; nt < 8; nt++) {
                const uint32_t* bh = &bfh[nt >> 1][(nt & 1) * 2];
                const uint32_t* bl = &bfl[nt >> 1][(nt & 1) * 2];
                mma16816(acc[mt][nt], afh[mt], bh);
                mma16816(acc[mt][nt], afh[mt], bl);
                mma16816(acc[mt][nt], afl[mt], bh);
            }

        // ---- k-slice 1 ----
        {
            const uint32_t ab = sb + a_off + 32u;
            #pragma unroll
            for (int mt = 0; mt < 4; mt++) {
                ldsm4(afh[mt], ab + mt*1280u);
                ldsm4(afl[mt], ab + mt*1280u + 10240u);
            }
            const uint32_t bb = sb + b_off + 32u;
            #pragma unroll
            for (int nt = 0; nt < 4; nt++) {
                ldsm4(bfh[nt], bb + nt*1280u);
                ldsm4(bfl[nt], bb + nt*1280u + 20480u);
            }
        }
        #pragma unroll
        for (int mt = 0; mt < 4; mt++)
            #pragma unroll
            for (int nt = 0; nt < 8; nt++) {
                const uint32_t* bh = &bfh[nt >> 1][(nt & 1) * 2];
                const uint32_t* bl = &bfl[nt >> 1][(nt & 1) * 2];
                mma16816(acc[mt][nt], afh[mt], bh);
                mma16816(acc[mt][nt], afh[mt], bl);
                mma16816(acc[mt][nt], afl[mt], bh);
            }
    }

    // ---------------- epilogue ----------------------------------------------------
    const int r0 = lane >> 2, c0 = (lane & 3) * 2;
    if (EPI != 4) {
        float*         Cbf = Cf + zb * sC;
        __nv_bfloat16* Cbh = Ch + zb * sC;
        __nv_bfloat16* Cbl = Cl + zb * sC;
        const float*   Rb  = res + zb * sC;
        #pragma unroll
        for (int mt = 0; mt < 4; mt++)
            #pragma unroll
            for (int nt = 0; nt < 8; nt++) {
                const int n = warp_n*64 + nt*8 + c0;
                float2 bv = make_float2(0.f, 0.f);
                if (EPI >= 1) bv = *(const float2*)&bias[n0 + n];
                #pragma unroll
                for (int hh = 0; hh < 2; hh++) {
                    const int m = warp_m*64 + mt*16 + r0 + hh*8;
                    float v0 = acc[mt][nt][hh*2], v1 = acc[mt][nt][hh*2+1];
                    if (EPI >= 1) { v0 += bv.x; v1 += bv.y; }
                    if (EPI >= 2) { v0 = gelu_f(v0); v1 = gelu_f(v1); }
                    const long long idx = (m0 + m) * (long long)N + n0 + n;
                    if (EPI == 3) {
                        float2 rv = *(const float2*)&Rb[idx];
                        v0 += rv.x; v1 += rv.y;
                    }
                    if (OUT == 0) {
                        *(float2*)&Cbf[idx] = make_float2(v0, v1);
                    } else {
                        __nv_bfloat162 h, l; split2(v0, v1, h, l);
                        *(__nv_bfloat162*)&Cbh[idx] = h;
                        *(__nv_bfloat162*)&Cbl[idx] = l;
                    }
                }
            }
    } else {
        // bias+gelu, then transposed split store: bodyT[b][n][t]
        __syncthreads();
        float* st = (float*)smc;                  // 128 rows x 256 cols, stride 260
        #pragma unroll
        for (int mt = 0; mt < 4; mt++)
            #pragma unroll
            for (int nt = 0; nt < 8; nt++) {
                const int n = warp_n*64 + nt*8 + c0;
                const float2 bv = *(const float2*)&bias[n0 + n];
                #pragma unroll
                for (int hh = 0; hh < 2; hh++) {
                    const int m = warp_m*64 + mt*16 + r0 + hh*8;
                    st[m*260 + n]     = gelu_f(acc[mt][nt][hh*2]   + bv.x);
                    st[m*260 + n + 1] = gelu_f(acc[mt][nt][hh*2+1] + bv.y);
                }
            }
        __syncthreads();
        const int b  = (int)(m0 >> 11);
        const int t0 = (int)(m0 & 2047);
        for (int e = tid; e < 256 * 64; e += 256) {
            const int n  = e >> 6;
            const int tp = (e & 63) * 2;
            const float v0 = st[tp*260 + n], v1 = st[(tp+1)*260 + n];
            __nv_bfloat162 h, l; split2(v0, v1, h, l);
            const long long idx = ((long long)b * DD + n0 + n) * TT + t0 + tp;
            *(__nv_bfloat162*)&Ch[idx] = h;
            *(__nv_bfloat162*)&Cl[idx] = l;
        }
    }
}

// ---------------- fp32 -> split bf16 -------------------------------------------
__global__ void __launch_bounds__(256)
convsplit(const float* __restrict__ x, __nv_bfloat16* __restrict__ xh,
          __nv_bfloat16* __restrict__ xl, int n4)
{
    int i = blockIdx.x * 256 + threadIdx.x;
    if (i >= n4) return;
    float4 v = ((const float4*)x)[i];
    __nv_bfloat162 h0, l0, h1, l1;
    split2(v.x, v.y, h0, l0);
    split2(v.z, v.w, h1, l1);
    ((__nv_bfloat162*)xh)[i*2]   = h0;  ((__nv_bfloat162*)xh)[i*2+1] = h1;
    ((__nv_bfloat162*)xl)[i*2]   = l0;  ((__nv_bfloat162*)xl)[i*2+1] = l1;
}

// ---------------- weight transpose + split --------------------------------------
__global__ void __launch_bounds__(256)
wtrans_split(const float* __restrict__ src, __nv_bfloat16* __restrict__ dh,
             __nv_bfloat16* __restrict__ dl, int R, int Cc)
{
    __shared__ float t[32][33];
    int x = blockIdx.x * 32 + threadIdx.x;
    int y = blockIdx.y * 32 + threadIdx.y;
    #pragma unroll
    for (int j = 0; j < 32; j += 8) t[threadIdx.y + j][threadIdx.x] = src[(long long)(y + j) * Cc + x];
    __syncthreads();
    x = blockIdx.y * 32 + threadIdx.x;
    y = blockIdx.x * 32 + threadIdx.y;
    #pragma unroll
    for (int j = 0; j < 32; j += 8) {
        float v = t[threadIdx.x][threadIdx.y + j];
        __nv_bfloat16 h = __float2bfloat16_rn(v);
        long long idx = (long long)(y + j) * R + x;
        dh[idx] = h;
        dl[idx] = __float2bfloat16_rn(v - __bfloat162float(h));
    }
}

// ---------------- softmax rows of 2048, split-bf16 in/out ------------------------
__global__ void __launch_bounds__(256)
softmax2048s(__nv_bfloat16* __restrict__ Sh, __nv_bfloat16* __restrict__ Sl)
{
    __shared__ float sh[8];
    const long long base = (long long)blockIdx.x * TT;
    const int tid = threadIdx.x, lane = tid & 31, warp = tid >> 5;

    float x[8];
    {
        uint4 hv = *(const uint4*)(Sh + base + tid * 8);
        uint4 lv = *(const uint4*)(Sl + base + tid * 8);
        const uint32_t hr[4] = {hv.x, hv.y, hv.z, hv.w};
        const uint32_t lr[4] = {lv.x, lv.y, lv.z, lv.w};
        #pragma unroll
        for (int i = 0; i < 4; i++) {
            float2 h2 = __bfloat1622float2(*(const __nv_bfloat162*)&hr[i]);
            float2 l2 = __bfloat1622float2(*(const __nv_bfloat162*)&lr[i]);
            x[i*2]   = h2.x + l2.x;
            x[i*2+1] = h2.y + l2.y;
        }
    }
    float m = x[0];
    #pragma unroll
    for (int i = 1; i < 8; i++) m = fmaxf(m, x[i]);
    #pragma unroll
    for (int o = 16; o > 0; o >>= 1) m = fmaxf(m, __shfl_xor_sync(0xffffffffu, m, o));
    if (lane == 0) sh[warp] = m;
    __syncthreads();
    if (tid == 0) { float mm = sh[0]; for (int w = 1; w < 8; w++) mm = fmaxf(mm, sh[w]); sh[0] = mm; }
    __syncthreads();
    const float rmax = sh[0];
    __syncthreads();
    float e[8], s = 0.0f;
    #pragma unroll
    for (int i = 0; i < 8; i++) { e[i] = __expf(x[i] - rmax); s += e[i]; }
    #pragma unroll
    for (int o = 16; o > 0; o >>= 1) s += __shfl_xor_sync(0xffffffffu, s, o);
    if (lane == 0) sh[warp] = s;
    __syncthreads();
    if (tid == 0) { float ss = 0; for (int w = 0; w < 8; w++) ss += sh[w]; sh[0] = ss; }
    __syncthreads();
    const float inv = 1.0f / sh[0];
    #pragma unroll
    for (int i = 0; i < 4; i++) {
        __nv_bfloat162 h, l;
        split2(e[i*2] * inv, e[i*2+1] * inv, h, l);
        *(__nv_bfloat162*)&Sh[base + tid*8 + i*2] = h;
        *(__nv_bfloat162*)&Sl[base + tid*8 + i*2] = l;
    }
}

// ---------------- layernorm rows of 512 -> fp32 + split -------------------------
__global__ void __launch_bounds__(128)
layernorm512s(const float* __restrict__ X, float* __restrict__ Y,
              __nv_bfloat16* __restrict__ Yh, __nv_bfloat16* __restrict__ Yl,
              const float* __restrict__ g, const float* __restrict__ b)
{
    __shared__ float shs[4], shq[4];
    const long long base = (long long)blockIdx.x * DD;
    const float* x = X + base;
    const int tid = threadIdx.x, lane = tid & 31, warp = tid >> 5;
    float4 v = *(const float4*)(x + tid * 4);
    float s = v.x + v.y + v.z + v.w;
    float q = v.x*v.x + v.y*v.y + v.z*v.z + v.w*v.w;
    #pragma unroll
    for (int o = 16; o > 0; o >>= 1) {
        s += __shfl_xor_sync(0xffffffffu, s, o);
        q += __shfl_xor_sync(0xffffffffu, q, o);
    }
    if (lane == 0) { shs[warp] = s; shq[warp] = q; }
    __syncthreads();
    if (tid == 0) { shs[0] = shs[0]+shs[1]+shs[2]+shs[3]; shq[0] = shq[0]+shq[1]+shq[2]+shq[3]; }
    __syncthreads();
    const float mu  = shs[0] * (1.0f / DD);
    const float var = shq[0] * (1.0f / DD) - mu * mu;
    const float r = rsqrtf(var + 1e-5f);
    float4 gg = *(const float4*)(g + tid * 4);
    float4 bb = *(const float4*)(b + tid * 4);
    float4 o;
    o.x = (v.x - mu) * r * gg.x + bb.x;
    o.y = (v.y - mu) * r * gg.y + bb.y;
    o.z = (v.z - mu) * r * gg.z + bb.z;
    o.w = (v.w - mu) * r * gg.w + bb.w;
    *(float4*)(Y + base + tid * 4) = o;
    __nv_bfloat162 h0, l0, h1, l1;
    split2(o.x, o.y, h0, l0);
    split2(o.z, o.w, h1, l1);
    *(__nv_bfloat162*)&Yh[base + tid*4]     = h0;
    *(__nv_bfloat162*)&Yh[base + tid*4 + 2] = h1;
    *(__nv_bfloat162*)&Yl[base + tid*4]     = l0;
    *(__nv_bfloat162*)&Yl[base + tid*4 + 2] = l1;
}

// ---------------- launch ----------------------------------------------------------
extern "C" void kernel_launch(void* const* d_in, const int* in_sizes, int n_in,
                              void* d_out, int out_size)
{
    const float* left  = (const float*)d_in[0];
    const float* right = (const float*)d_in[1];
    const float* body  = (const float*)d_in[2];
    const float* Wl = (const float*)d_in[3];  const float* bl = (const float*)d_in[4];
    const float* Wr = (const float*)d_in[5];  const float* br = (const float*)d_in[6];
    const float* Wb = (const float*)d_in[7];  const float* bbv = (const float*)d_in[8];
    const float* Wo = (const float*)d_in[9];  const float* bo = (const float*)d_in[10];
    const float* ln_g = (const float*)d_in[11]; const float* ln_b = (const float*)d_in[12];
    const float* W1 = (const float*)d_in[13]; const float* b1 = (const float*)d_in[14];
    const float* lg2 = (const float*)d_in[15]; const float* lb2 = (const float*)d_in[16];
    const float* W2 = (const float*)d_in[17]; const float* b2 = (const float*)d_in[18];
    const float* W3 = (const float*)d_in[19]; const float* b3 = (const float*)d_in[20];
    float* out = (float*)d_out;

    float *t2, *ln1;
    __nv_bfloat16 *Sh, *Sl, *eh, *el, *loh, *lol, *roh, *rol, *bth, *btl;
    __nv_bfloat16 *t1h, *t1l, *l1h, *l1l, *l2h, *l2l, *mh, *ml;
    __nv_bfloat16 *WlTh,*WlTl,*WrTh,*WrTl,*WbTh,*WbTl,*WoTh,*WoTl,*W1Th,*W1Tl,*W2Th,*W2Tl,*W3Th,*W3Tl;
    cudaGetSymbolAddress((void**)&Sh,  g_Sh);  cudaGetSymbolAddress((void**)&Sl,  g_Sl);
    cudaGetSymbolAddress((void**)&eh,  g_eh);  cudaGetSymbolAddress((void**)&el,  g_el);
    cudaGetSymbolAddress((void**)&loh, g_loh); cudaGetSymbolAddress((void**)&lol, g_lol);
    cudaGetSymbolAddress((void**)&roh, g_roh); cudaGetSymbolAddress((void**)&rol, g_rol);
    cudaGetSymbolAddress((void**)&bth, g_bth); cudaGetSymbolAddress((void**)&btl, g_btl);
    cudaGetSymbolAddress((void**)&t1h, g_t1h); cudaGetSymbolAddress((void**)&t1l, g_t1l);
    cudaGetSymbolAddress((void**)&t2,  g_t2);  cudaGetSymbolAddress((void**)&ln1, g_ln1);
    cudaGetSymbolAddress((void**)&l1h, g_l1h); cudaGetSymbolAddress((void**)&l1l, g_l1l);
    cudaGetSymbolAddress((void**)&l2h, g_l2h); cudaGetSymbolAddress((void**)&l2l, g_l2l);
    cudaGetSymbolAddress((void**)&mh,  g_mh);  cudaGetSymbolAddress((void**)&ml,  g_ml);
    cudaGetSymbolAddress((void**)&WlTh,g_WlTh);cudaGetSymbolAddress((void**)&WlTl,g_WlTl);
    cudaGetSymbolAddress((void**)&WrTh,g_WrTh);cudaGetSymbolAddress((void**)&WrTl,g_WrTl);
    cudaGetSymbolAddress((void**)&WbTh,g_WbTh);cudaGetSymbolAddress((void**)&WbTl,g_WbTl);
    cudaGetSymbolAddress((void**)&WoTh,g_WoTh);cudaGetSymbolAddress((void**)&WoTl,g_WoTl);
    cudaGetSymbolAddress((void**)&W1Th,g_W1Th);cudaGetSymbolAddress((void**)&W1Tl,g_W1Tl);
    cudaGetSymbolAddress((void**)&W2Th,g_W2Th);cudaGetSymbolAddress((void**)&W2Tl,g_W2Tl);
    cudaGetSymbolAddress((void**)&W3Th,g_W3Th);cudaGetSymbolAddress((void**)&W3Tl,g_W3Tl);

    cudaFuncSetAttribute(gemm_mma<0,1>, cudaFuncAttributeMaxDynamicSharedMemorySize, SMEM_BYTES);
    cudaFuncSetAttribute(gemm_mma<1,0>, cudaFuncAttributeMaxDynamicSharedMemorySize, SMEM_BYTES);
    cudaFuncSetAttribute(gemm_mma<2,1>, cudaFuncAttributeMaxDynamicSharedMemorySize, SMEM_BYTES);
    cudaFuncSetAttribute(gemm_mma<3,0>, cudaFuncAttributeMaxDynamicSharedMemorySize, SMEM_BYTES);
    cudaFuncSetAttribute(gemm_mma<4,1>, cudaFuncAttributeMaxDynamicSharedMemorySize, SMEM_BYTES);

    const long long sTD = (long long)TT * DD;
    const long long sTT = (long long)TT * TT;
    dim3 tb(32, 8);
    const int n4 = BT * DD / 4;

    // weights: transpose + split
    wtrans_split<<<dim3(16,16), tb>>>(Wl, WlTh, WlTl, DD, DD);
    wtrans_split<<<dim3(16,16), tb>>>(Wr, WrTh, WrTl, DD, DD);
    wtrans_split<<<dim3(16,16), tb>>>(Wb, WbTh, WbTl, DD, DD);
    wtrans_split<<<dim3(16,16), tb>>>(Wo, WoTh, WoTl, DD, DD);
    wtrans_split<<<dim3(16,16), tb>>>(W1, W1Th, W1Tl, DD, DD);
    wtrans_split<<<dim3(48,16), tb>>>(W2, W2Th, W2Tl, DD, DMID);
    wtrans_split<<<dim3(16,48), tb>>>(W3, W3Th, W3Tl, DMID, DD);

    // projections (+GELU), split outputs
    convsplit<<<n4/256, 256>>>(left, eh, el, n4);
    gemm_mma<2,1><<<dim3(2,128,1), 256, SMEM_BYTES>>>(eh, el, WlTh, WlTl, bl, nullptr,
        nullptr, loh, lol, DD, DD, 0, 0, 0);
    convsplit<<<n4/256, 256>>>(right, eh, el, n4);
    gemm_mma<2,1><<<dim3(2,128,1), 256, SMEM_BYTES>>>(eh, el, WrTh, WrTl, br, nullptr,
        nullptr, roh, rol, DD, DD, 0, 0, 0);
    convsplit<<<n4/256, 256>>>(body, eh, el, n4);
    gemm_mma<4,1><<<dim3(2,128,1), 256, SMEM_BYTES>>>(eh, el, WbTh, WbTl, bbv, nullptr,
        nullptr, bth, btl, DD, DD, 0, 0, 0);

    // attention: S = ro @ lo^T (split out) ; softmax in-place ; fuse = P @ bodyT^T
    gemm_mma<0,1><<<dim3(8,16,BB), 256, SMEM_BYTES>>>(roh, rol, loh, lol, nullptr, nullptr,
        nullptr, Sh, Sl, DD, TT, sTD, sTD, sTT);
    softmax2048s<<<BT, 256>>>(Sh, Sl);
    gemm_mma<0,1><<<dim3(2,16,BB), 256, SMEM_BYTES>>>(Sh, Sl, bth, btl, nullptr, nullptr,
        nullptr, t1h, t1l, TT, DD, sTT, sTD, sTD);

    // output projection + LN
    gemm_mma<1,0><<<dim3(2,128,1), 256, SMEM_BYTES>>>(t1h, t1l, WoTh, WoTl, bo, nullptr,
        t2, nullptr, nullptr, DD, DD, 0, 0, 0);
    layernorm512s<<<BT, 128>>>(t2, ln1, l1h, l1l, ln_g, ln_b);

    // inverted residual
    gemm_mma<3,0><<<dim3(2,128,1), 256, SMEM_BYTES>>>(l1h, l1l, W1Th, W1Tl, b1, ln1,
        t2, nullptr, nullptr, DD, DD, 0, 0, 0);
    layernorm512s<<<BT, 128>>>(t2, ln1, l2h, l2l, lg2, lb2);
    gemm_mma<2,1><<<dim3(6,128,1), 256, SMEM_BYTES>>>(l2h, l2l, W2Th, W2Tl, b2, nullptr,
        nullptr, mh, ml, DD, DMID, 0, 0, 0);
    gemm_mma<1,0><<<dim3(2,128,1), 256, SMEM_BYTES>>>(mh, ml, W3Th, W3Tl, b3, nullptr,
        out, nullptr, nullptr, DMID, DD, 0, 0, 0);
}